// round 5
// baseline (speedup 1.0000x reference)
#include <cuda_runtime.h>
#include <math.h>

#define FRAMES 32
#define FRAME_ELEMS (720*1280)          // 921600
#define TOTAL_ELEMS (FRAMES*FRAME_ELEMS)
#define NB 65536                        // bit-binning: encF(p) >> 16 (monotone)
#define SPAN 256                        // bins per epilogue thread (NB/TPB)
#define BPF 225                         // blocks per frame: 225*256*16 = 921600
#define TPB 256
#define NBLK (BPF*FRAMES)

// All fields are valid when zero-initialized (mins stored as max of ~encF).
struct Stats {
    double sum_p[FRAMES];
    double sum_p2[FRAMES];
    double sum_fp[FRAMES];
    double cnt_fix[FRAMES];
    double sum_sim[FRAMES];
    double sum_g;
    unsigned pmin_c, gmin_c;     // global mins: stores max(~encF(x))
    float simc[4];               // pmin, gmin, invTp, invTg
};

__device__ Stats g_s;            // zero at module load; epilogue re-zeros each call
__device__ unsigned g_hf[NB];
__device__ unsigned g_hn[NB];
__device__ unsigned g_ticket1;
__device__ unsigned g_ticket2;

// ---------- helpers ----------
__device__ __forceinline__ unsigned encF(float x) {
    unsigned u = __float_as_uint(x);
    return (u & 0x80000000u) ? ~u : (u | 0x80000000u);
}
__device__ __forceinline__ float decF(unsigned u) {
    u = (u & 0x80000000u) ? (u & 0x7FFFFFFFu) : ~u;
    return __uint_as_float(u);
}

// 256-thread block reductions (f32)
__device__ __forceinline__ float blkSumF(float v, float* sh) {
    #pragma unroll
    for (int o = 16; o; o >>= 1) v += __shfl_down_sync(0xFFFFFFFFu, v, o);
    if ((threadIdx.x & 31) == 0) sh[threadIdx.x >> 5] = v;
    __syncthreads();
    float r = 0.f;
    if (threadIdx.x < 32) {
        r = (threadIdx.x < 8) ? sh[threadIdx.x] : 0.f;
        #pragma unroll
        for (int o = 4; o; o >>= 1) r += __shfl_down_sync(0xFFFFFFFFu, r, o);
    }
    __syncthreads();
    return r;   // valid on thread 0
}

__device__ __forceinline__ float blkMinF(float v, float* sh) {
    #pragma unroll
    for (int o = 16; o; o >>= 1) v = fminf(v, __shfl_down_sync(0xFFFFFFFFu, v, o));
    if ((threadIdx.x & 31) == 0) sh[threadIdx.x >> 5] = v;
    __syncthreads();
    float r = 3.4e38f;
    if (threadIdx.x < 32) {
        r = (threadIdx.x < 8) ? sh[threadIdx.x] : 3.4e38f;
        #pragma unroll
        for (int o = 4; o; o >>= 1) r = fminf(r, __shfl_down_sync(0xFFFFFFFFu, r, o));
    }
    __syncthreads();
    return r;
}

// ---------- Pass 1: NSS stats + global mins + frame-0 histogram ----------
__global__ void __launch_bounds__(TPB, 3) k_main(const float* __restrict__ pred,
                                                 const float* __restrict__ gt,
                                                 const int* __restrict__ fix) {
    __shared__ float shf[8];
    int f = blockIdx.y;
    size_t base = (size_t)f * FRAME_ELEMS + (size_t)blockIdx.x * 4096u;
    const float4* p4 = reinterpret_cast<const float4*>(pred + base);
    const float4* g4 = reinterpret_cast<const float4*>(gt + base);
    const int4*   x4 = reinterpret_cast<const int4*>(fix + base);

    // batch all loads first (MLP)
    float4 P[4], G[4]; int4 X[4];
    #pragma unroll
    for (int k = 0; k < 4; k++) P[k] = p4[threadIdx.x + 256 * k];
    #pragma unroll
    for (int k = 0; k < 4; k++) G[k] = g4[threadIdx.x + 256 * k];
    #pragma unroll
    for (int k = 0; k < 4; k++) X[k] = x4[threadIdx.x + 256 * k];

    bool doHist = (f == 0);

    float sp = 0.f, sp2 = 0.f, sfp = 0.f, sg = 0.f, cf = 0.f;
    float pmn = 3.4e38f, gmn = 3.4e38f;
    #pragma unroll
    for (int k = 0; k < 4; k++) {
        float4 p = P[k]; float4 g = G[k]; int4 x = X[k];
        sp  += (p.x + p.y) + (p.z + p.w);
        sp2 += (p.x*p.x + p.y*p.y) + (p.z*p.z + p.w*p.w);
        sg  += (g.x + g.y) + (g.z + g.w);
        pmn = fminf(pmn, fminf(fminf(p.x, p.y), fminf(p.z, p.w)));
        gmn = fminf(gmn, fminf(fminf(g.x, g.y), fminf(g.z, g.w)));
        if (x.x) { sfp += p.x; cf += 1.f; }
        if (x.y) { sfp += p.y; cf += 1.f; }
        if (x.z) { sfp += p.z; cf += 1.f; }
        if (x.w) { sfp += p.w; cf += 1.f; }
        if (doHist) {
            // order-preserving bit-binning: rank-equivalent, no min/max needed
            unsigned b0 = encF(p.x) >> 16;
            unsigned b1 = encF(p.y) >> 16;
            unsigned b2 = encF(p.z) >> 16;
            unsigned b3 = encF(p.w) >> 16;
            atomicAdd(x.x ? &g_hf[b0] : &g_hn[b0], 1u);
            atomicAdd(x.y ? &g_hf[b1] : &g_hn[b1], 1u);
            atomicAdd(x.z ? &g_hf[b2] : &g_hn[b2], 1u);
            atomicAdd(x.w ? &g_hf[b3] : &g_hn[b3], 1u);
        }
    }
    float rs  = blkSumF(sp,  shf);
    float rs2 = blkSumF(sp2, shf);
    float rfp = blkSumF(sfp, shf);
    float rg  = blkSumF(sg,  shf);
    float rcf = blkSumF(cf,  shf);
    float rpmn = blkMinF(pmn, shf);
    float rgmn = blkMinF(gmn, shf);
    if (threadIdx.x == 0) {
        atomicAdd(&g_s.sum_p[f],  (double)rs);
        atomicAdd(&g_s.sum_p2[f], (double)rs2);
        atomicAdd(&g_s.sum_fp[f], (double)rfp);
        atomicAdd(&g_s.cnt_fix[f], (double)rcf);
        atomicAdd(&g_s.sum_g,     (double)rg);
        atomicMax(&g_s.pmin_c, ~encF(rpmn));
        atomicMax(&g_s.gmin_c, ~encF(rgmn));
        __threadfence();
        unsigned tk = atomicAdd(&g_ticket1, 1u);
        if (tk == NBLK - 1u) {
            // last block: finalize SIM normalization constants
            float pmin = decF(~g_s.pmin_c);
            float gmin = decF(~g_s.gmin_c);
            double sumP = 0.0;
            #pragma unroll
            for (int ff = 0; ff < FRAMES; ff++) sumP += __ldcg(&g_s.sum_p[ff]);
            double Tp = sumP - (double)TOTAL_ELEMS * (double)pmin;
            double Tg = __ldcg(&g_s.sum_g) - (double)TOTAL_ELEMS * (double)gmin;
            g_s.simc[0] = pmin;
            g_s.simc[1] = gmin;
            g_s.simc[2] = (float)(1.0 / Tp);
            g_s.simc[3] = (float)(1.0 / Tg);
        }
    }
}

// ---------- Pass 2: SIM; last-finishing block runs AUC + full epilogue ----------
__global__ void __launch_bounds__(TPB, 4) k_sim(const float* __restrict__ pred,
                                                const float* __restrict__ gt,
                                                float* __restrict__ out) {
    __shared__ float shf[8];
    int f  = (FRAMES - 1) - blockIdx.y;
    int xb = (BPF - 1) - blockIdx.x;
    size_t base = (size_t)f * FRAME_ELEMS + (size_t)xb * 4096u;
    const float4* p4 = reinterpret_cast<const float4*>(pred + base);
    const float4* g4 = reinterpret_cast<const float4*>(gt + base);

    float pmin = g_s.simc[0], gmin = g_s.simc[1];
    float ip   = g_s.simc[2], ig   = g_s.simc[3];

    float4 P[4], G[4];
    #pragma unroll
    for (int k = 0; k < 4; k++) P[k] = p4[threadIdx.x + 256 * k];
    #pragma unroll
    for (int k = 0; k < 4; k++) G[k] = g4[threadIdx.x + 256 * k];

    float acc = 0.f;
    #pragma unroll
    for (int k = 0; k < 4; k++) {
        float4 p = P[k]; float4 g = G[k];
        if (g.x > gmin) acc += fminf((g.x - gmin) * ig, (p.x - pmin) * ip);
        if (g.y > gmin) acc += fminf((g.y - gmin) * ig, (p.y - pmin) * ip);
        if (g.z > gmin) acc += fminf((g.z - gmin) * ig, (p.z - pmin) * ip);
        if (g.w > gmin) acc += fminf((g.w - gmin) * ig, (p.w - pmin) * ip);
    }
    float r = blkSumF(acc, shf);

    __shared__ int sLast;
    if (threadIdx.x == 0) {
        atomicAdd(&g_s.sum_sim[f], (double)r);
        __threadfence();
        unsigned tk = atomicAdd(&g_ticket2, 1u);
        sLast = (tk == NBLK - 1u) ? 1 : 0;
    }
    __syncthreads();
    if (!sLast) return;

    // ======== epilogue (one 256-thread block) ========
    __shared__ unsigned swt[8];
    __shared__ unsigned long long sU[3];
    __shared__ int sB;
    int t = threadIdx.x;
    int lane = t & 31, wid = t >> 5;
    if (t == 0) { sB = NB; sU[0] = 0ull; sU[1] = 0ull; sU[2] = 0ull; }

    const uint4* hf4 = reinterpret_cast<const uint4*>(g_hf);
    const uint4* hn4 = reinterpret_cast<const uint4*>(g_hn);

    // Pass A: per-thread fix-count + lowest fixation bin over bins [t*SPAN, (t+1)*SPAN)
    unsigned sumF = 0; int mn = NB;
    #pragma unroll 8
    for (int i = 0; i < SPAN / 4; i++) {
        uint4 h = hf4[t * (SPAN / 4) + i];
        sumF += h.x + h.y + h.z + h.w;
        int bb = t * SPAN + i * 4;
        if (h.x && bb     < mn) mn = bb;
        if (h.y && bb + 1 < mn) mn = bb + 1;
        if (h.z && bb + 2 < mn) mn = bb + 2;
        if (h.w && bb + 3 < mn) mn = bb + 3;
    }
    // block-exclusive scan of sumF (warp scan + warp totals)
    unsigned incl = sumF;
    #pragma unroll
    for (int o = 1; o < 32; o <<= 1) {
        unsigned v = __shfl_up_sync(0xFFFFFFFFu, incl, o);
        if (lane >= o) incl += v;
    }
    if (lane == 31) swt[wid] = incl;
    // warp-reduce mn, lane0 -> shared atomicMin
    #pragma unroll
    for (int o = 16; o; o >>= 1) mn = min(mn, __shfl_down_sync(0xFFFFFFFFu, mn, o));
    __syncthreads();                       // swt + sB init visible
    if (lane == 0) atomicMin(&sB, mn);
    if (t < 8) {
        unsigned w = swt[t];
        unsigned s = w;
        #pragma unroll
        for (int o = 1; o < 8; o <<= 1) {
            unsigned v = __shfl_up_sync(0xFFu, s, o);
            if (t >= o) s += v;
        }
        swt[t] = s - w;                    // exclusive warp offsets
    }
    __syncthreads();
    unsigned F = swt[wid] + (incl - sumF); // exclusive prefix of fix counts
    int bstar = sB;

    // Pass B: Mann-Whitney accumulation
    unsigned long long u1 = 0, u2 = 0, cntN = 0;
    #pragma unroll 8
    for (int i = 0; i < SPAN / 4; i++) {
        uint4 h = hf4[t * (SPAN / 4) + i];
        uint4 n = hn4[t * (SPAN / 4) + i];
        int bb = t * SPAN + i * 4;
        u1 += (unsigned long long)n.x * F; u2 += (unsigned long long)h.x * n.x; if (bb     <= bstar) cntN += n.x; F += h.x;
        u1 += (unsigned long long)n.y * F; u2 += (unsigned long long)h.y * n.y; if (bb + 1 <= bstar) cntN += n.y; F += h.y;
        u1 += (unsigned long long)n.z * F; u2 += (unsigned long long)h.z * n.z; if (bb + 2 <= bstar) cntN += n.z; F += h.z;
        u1 += (unsigned long long)n.w * F; u2 += (unsigned long long)h.w * n.w; if (bb + 3 <= bstar) cntN += n.w; F += h.w;
    }
    #pragma unroll
    for (int o = 16; o; o >>= 1) {
        u1   += __shfl_down_sync(0xFFFFFFFFu, u1, o);
        u2   += __shfl_down_sync(0xFFFFFFFFu, u2, o);
        cntN += __shfl_down_sync(0xFFFFFFFFu, cntN, o);
    }
    if (lane == 0) {
        atomicAdd(&sU[0], u1);
        atomicAdd(&sU[1], u2);
        atomicAdd(&sU[2], cntN);
    }
    __syncthreads();

    // parallel FP64 per-frame epilogue on warp 0 (thread f = frame f)
    if (wid == 0) {
        double Np = (double)FRAME_ELEMS;
        double m   = __ldcg(&g_s.sum_p[lane]) / Np;
        double var = __ldcg(&g_s.sum_p2[lane]) / Np - m * m;
        double sd  = sqrt(var);
        double c   = __ldcg(&g_s.cnt_fix[lane]);
        double nssf = (__ldcg(&g_s.sum_fp[lane]) - c * m) / (sd * c);
        double simf = __ldcg(&g_s.sum_sim[lane]);
        double Nf0 = __shfl_sync(0xFFFFFFFFu, c, 0);
        #pragma unroll
        for (int o = 16; o; o >>= 1) {
            nssf += __shfl_down_sync(0xFFFFFFFFu, nssf, o);
            simf += __shfl_down_sync(0xFFFFFFFFu, simf, o);
        }
        if (lane == 0) {
            double Nf = Nf0;
            double D  = Np - Nf;
            double S  = (double)sU[0] + 0.5 * (double)sU[1];
            double b  = (Np - Nf) - (double)sU[2];   // non-fix strictly above bstar
            double auc = ((2.0 * Nf + 1.0) * b + 1.0 - 2.0 * S) / (2.0 * Nf * D)
                       + 1.0 - (b + 1.0) / D;
            double sim = simf / (double)FRAMES;
            double nss = nssf / (double)FRAMES;
            double loss = auc + sim + nss;
            out[0] = (float)loss;
            out[1] = (float)auc;
            out[2] = (float)sim;
            out[3] = (float)nss;
        }
    }

    // ---- self-clean device state for the next graph replay ----
    __syncthreads();   // all reads of g_hf/g_hn/g_s complete
    uint4* hf4w = reinterpret_cast<uint4*>(g_hf);
    uint4* hn4w = reinterpret_cast<uint4*>(g_hn);
    uint4 z = make_uint4(0, 0, 0, 0);
    #pragma unroll 8
    for (int i = 0; i < SPAN / 4; i++) {
        hf4w[t * (SPAN / 4) + i] = z;
        hn4w[t * (SPAN / 4) + i] = z;
    }
    {
        unsigned long long* s8 = reinterpret_cast<unsigned long long*>(&g_s);
        int n8 = (int)(sizeof(Stats) / 8);
        if (t < n8) s8[t] = 0ull;
        if (t == 0) {
            char* sc8 = reinterpret_cast<char*>(&g_s);
            for (int i = n8 * 8; i < (int)sizeof(Stats); i++) sc8[i] = 0;
            g_ticket1 = 0u;
            g_ticket2 = 0u;
        }
    }
}

extern "C" void kernel_launch(void* const* d_in, const int* in_sizes, int n_in,
                              void* d_out, int out_size) {
    const float* pred = (const float*)d_in[0];
    const float* gt   = (const float*)d_in[1];
    const int*   fix  = (const int*)d_in[2];
    float* out = (float*)d_out;

    dim3 gfull(BPF, FRAMES);
    k_main<<<gfull, TPB>>>(pred, gt, fix);
    k_sim<<<gfull, TPB>>>(pred, gt, out);
}

// round 6
// speedup vs baseline: 1.9204x; 1.9204x over previous
#include <cuda_runtime.h>
#include <math.h>

#define FRAMES 32
#define FRAME_ELEMS (720*1280)          // 921600
#define TOTAL_ELEMS (FRAMES*FRAME_ELEMS)
#define NB 8192                         // 64KB histograms -> L2-resident
#define SPAN 32                         // bins per epilogue thread (NB/256)
#define BPF 225                         // blocks per frame: 225*256*16 = 921600
#define TPB 256
#define NBLK (BPF*FRAMES)

// All fields valid when zero-initialized (mins stored as max of ~encF).
struct Stats {
    double sum_p[FRAMES];
    double sum_p2[FRAMES];
    double sum_fp[FRAMES];
    double cnt_fix[FRAMES];
    double sum_sim[FRAMES];
    double sum_g;
    unsigned pmin_c, gmin_c;     // global mins: stores max(~encF(x))
    unsigned p0min_c, p0max_e;   // frame-0 pred min (complement) / max (direct)
    float simc[4];               // pmin, gmin, invTp, invTg
};

__device__ Stats g_s;            // zero at module load; k_auc re-zeros each call
__device__ unsigned g_hf[NB];
__device__ unsigned g_hn[NB];
__device__ unsigned g_ticket1;   // k_main completion ticket
__device__ unsigned g_ticket2;   // k_auc hist completion ticket

// ---------- helpers ----------
__device__ __forceinline__ unsigned encF(float x) {
    unsigned u = __float_as_uint(x);
    return (u & 0x80000000u) ? ~u : (u | 0x80000000u);
}
__device__ __forceinline__ float decF(unsigned u) {
    u = (u & 0x80000000u) ? (u & 0x7FFFFFFFu) : ~u;
    return __uint_as_float(u);
}

__device__ __forceinline__ float blkSumF(float v, float* sh) {
    #pragma unroll
    for (int o = 16; o; o >>= 1) v += __shfl_down_sync(0xFFFFFFFFu, v, o);
    if ((threadIdx.x & 31) == 0) sh[threadIdx.x >> 5] = v;
    __syncthreads();
    float r = 0.f;
    if (threadIdx.x < 32) {
        r = (threadIdx.x < 8) ? sh[threadIdx.x] : 0.f;
        #pragma unroll
        for (int o = 4; o; o >>= 1) r += __shfl_down_sync(0xFFFFFFFFu, r, o);
    }
    __syncthreads();
    return r;   // valid on thread 0
}

__device__ __forceinline__ float blkMinF(float v, float* sh) {
    #pragma unroll
    for (int o = 16; o; o >>= 1) v = fminf(v, __shfl_down_sync(0xFFFFFFFFu, v, o));
    if ((threadIdx.x & 31) == 0) sh[threadIdx.x >> 5] = v;
    __syncthreads();
    float r = 3.4e38f;
    if (threadIdx.x < 32) {
        r = (threadIdx.x < 8) ? sh[threadIdx.x] : 3.4e38f;
        #pragma unroll
        for (int o = 4; o; o >>= 1) r = fminf(r, __shfl_down_sync(0xFFFFFFFFu, r, o));
    }
    __syncthreads();
    return r;
}

__device__ __forceinline__ float blkMaxF(float v, float* sh) {
    #pragma unroll
    for (int o = 16; o; o >>= 1) v = fmaxf(v, __shfl_down_sync(0xFFFFFFFFu, v, o));
    if ((threadIdx.x & 31) == 0) sh[threadIdx.x >> 5] = v;
    __syncthreads();
    float r = -3.4e38f;
    if (threadIdx.x < 32) {
        r = (threadIdx.x < 8) ? sh[threadIdx.x] : -3.4e38f;
        #pragma unroll
        for (int o = 4; o; o >>= 1) r = fmaxf(r, __shfl_down_sync(0xFFFFFFFFu, r, o));
    }
    __syncthreads();
    return r;
}

// ---------- Pass 1: NSS stats + global mins + frame-0 min/max ----------
__global__ void __launch_bounds__(TPB, 3) k_main(const float* __restrict__ pred,
                                                 const float* __restrict__ gt,
                                                 const int* __restrict__ fix) {
    __shared__ float shf[8];
    int f = blockIdx.y;
    size_t base = (size_t)f * FRAME_ELEMS + (size_t)blockIdx.x * 4096u;
    const float4* p4 = reinterpret_cast<const float4*>(pred + base);
    const float4* g4 = reinterpret_cast<const float4*>(gt + base);
    const int4*   x4 = reinterpret_cast<const int4*>(fix + base);

    // batch all loads first (MLP)
    float4 P[4], G[4]; int4 X[4];
    #pragma unroll
    for (int k = 0; k < 4; k++) P[k] = p4[threadIdx.x + 256 * k];
    #pragma unroll
    for (int k = 0; k < 4; k++) G[k] = g4[threadIdx.x + 256 * k];
    #pragma unroll
    for (int k = 0; k < 4; k++) X[k] = x4[threadIdx.x + 256 * k];

    float sp = 0.f, sp2 = 0.f, sfp = 0.f, sg = 0.f, cf = 0.f;
    float pmn = 3.4e38f, gmn = 3.4e38f, pmx = -3.4e38f;
    #pragma unroll
    for (int k = 0; k < 4; k++) {
        float4 p = P[k]; float4 g = G[k]; int4 x = X[k];
        sp  += (p.x + p.y) + (p.z + p.w);
        sp2 += (p.x*p.x + p.y*p.y) + (p.z*p.z + p.w*p.w);
        sg  += (g.x + g.y) + (g.z + g.w);
        pmn = fminf(pmn, fminf(fminf(p.x, p.y), fminf(p.z, p.w)));
        pmx = fmaxf(pmx, fmaxf(fmaxf(p.x, p.y), fmaxf(p.z, p.w)));
        gmn = fminf(gmn, fminf(fminf(g.x, g.y), fminf(g.z, g.w)));
        if (x.x) { sfp += p.x; cf += 1.f; }
        if (x.y) { sfp += p.y; cf += 1.f; }
        if (x.z) { sfp += p.z; cf += 1.f; }
        if (x.w) { sfp += p.w; cf += 1.f; }
    }
    float rs  = blkSumF(sp,  shf);
    float rs2 = blkSumF(sp2, shf);
    float rfp = blkSumF(sfp, shf);
    float rg  = blkSumF(sg,  shf);
    float rcf = blkSumF(cf,  shf);
    float rpmn = blkMinF(pmn, shf);
    float rgmn = blkMinF(gmn, shf);
    float rpmx = blkMaxF(pmx, shf);
    if (threadIdx.x == 0) {
        atomicAdd(&g_s.sum_p[f],  (double)rs);
        atomicAdd(&g_s.sum_p2[f], (double)rs2);
        atomicAdd(&g_s.sum_fp[f], (double)rfp);
        atomicAdd(&g_s.cnt_fix[f], (double)rcf);
        atomicAdd(&g_s.sum_g,     (double)rg);
        atomicMax(&g_s.pmin_c, ~encF(rpmn));
        atomicMax(&g_s.gmin_c, ~encF(rgmn));
        if (f == 0) {
            atomicMax(&g_s.p0min_c, ~encF(rpmn));
            atomicMax(&g_s.p0max_e, encF(rpmx));
        }
        __threadfence();
        unsigned tk = atomicAdd(&g_ticket1, 1u);
        if (tk == NBLK - 1u) {
            // last block: finalize SIM normalization constants
            float pmin = decF(~g_s.pmin_c);
            float gmin = decF(~g_s.gmin_c);
            double sumP = 0.0;
            #pragma unroll
            for (int ff = 0; ff < FRAMES; ff++) sumP += __ldcg(&g_s.sum_p[ff]);
            double Tp = sumP - (double)TOTAL_ELEMS * (double)pmin;
            double Tg = __ldcg(&g_s.sum_g) - (double)TOTAL_ELEMS * (double)gmin;
            g_s.simc[0] = pmin;
            g_s.simc[1] = gmin;
            g_s.simc[2] = (float)(1.0 / Tp);
            g_s.simc[3] = (float)(1.0 / Tg);
        }
    }
}

// ---------- Pass 2: SIM only (lean). Reversed order ends on frame 0 (L2-warm for k_auc). ----------
__global__ void __launch_bounds__(TPB, 4) k_sim(const float* __restrict__ pred,
                                                const float* __restrict__ gt) {
    __shared__ float shf[8];
    int f  = (FRAMES - 1) - blockIdx.y;
    int xb = (BPF - 1) - blockIdx.x;
    size_t base = (size_t)f * FRAME_ELEMS + (size_t)xb * 4096u;
    const float4* p4 = reinterpret_cast<const float4*>(pred + base);
    const float4* g4 = reinterpret_cast<const float4*>(gt + base);

    float pmin = g_s.simc[0], gmin = g_s.simc[1];
    float ip   = g_s.simc[2], ig   = g_s.simc[3];

    float4 P[4], G[4];
    #pragma unroll
    for (int k = 0; k < 4; k++) P[k] = p4[threadIdx.x + 256 * k];
    #pragma unroll
    for (int k = 0; k < 4; k++) G[k] = g4[threadIdx.x + 256 * k];

    float acc = 0.f;
    #pragma unroll
    for (int k = 0; k < 4; k++) {
        float4 p = P[k]; float4 g = G[k];
        if (g.x > gmin) acc += fminf((g.x - gmin) * ig, (p.x - pmin) * ip);
        if (g.y > gmin) acc += fminf((g.y - gmin) * ig, (p.y - pmin) * ip);
        if (g.z > gmin) acc += fminf((g.z - gmin) * ig, (p.z - pmin) * ip);
        if (g.w > gmin) acc += fminf((g.w - gmin) * ig, (p.w - pmin) * ip);
    }
    float r = blkSumF(acc, shf);
    if (threadIdx.x == 0) atomicAdd(&g_s.sum_sim[f], (double)r);
}

// ---------- Pass 3: frame-0 histogram + (last block) AUC + full epilogue ----------
__global__ void k_auc(const float* __restrict__ pred, const int* __restrict__ fix,
                      float* __restrict__ out) {
    int t = threadIdx.x;

    // --- hist phase: every block histograms its frame-0 tile (L2-warm) ---
    {
        float p0min = decF(~g_s.p0min_c);
        float p0max = decF(g_s.p0max_e);
        float scale = (float)NB / (p0max - p0min);
        size_t base = (size_t)blockIdx.x * 4096u;
        const float4* p4 = reinterpret_cast<const float4*>(pred + base);
        const int4*   x4 = reinterpret_cast<const int4*>(fix + base);
        float4 P[4]; int4 X[4];
        #pragma unroll
        for (int k = 0; k < 4; k++) P[k] = p4[t + 256 * k];
        #pragma unroll
        for (int k = 0; k < 4; k++) X[k] = x4[t + 256 * k];
        #pragma unroll
        for (int k = 0; k < 4; k++) {
            float4 p = P[k]; int4 x = X[k];
            int b0 = min(NB - 1, (int)((p.x - p0min) * scale));
            int b1 = min(NB - 1, (int)((p.y - p0min) * scale));
            int b2 = min(NB - 1, (int)((p.z - p0min) * scale));
            int b3 = min(NB - 1, (int)((p.w - p0min) * scale));
            atomicAdd(x.x ? &g_hf[b0] : &g_hn[b0], 1u);
            atomicAdd(x.y ? &g_hf[b1] : &g_hn[b1], 1u);
            atomicAdd(x.z ? &g_hf[b2] : &g_hn[b2], 1u);
            atomicAdd(x.w ? &g_hf[b3] : &g_hn[b3], 1u);
        }
    }
    __threadfence();            // make this thread's atomics globally visible
    __syncthreads();            // all threads' fences done
    __shared__ int sLast;
    if (t == 0) {
        unsigned tk = atomicAdd(&g_ticket2, 1u);
        sLast = (tk == BPF - 1u) ? 1 : 0;
    }
    __syncthreads();
    if (!sLast) return;

    // --- epilogue on the last-finishing block (hist now complete, L2-hot) ---
    __shared__ unsigned swt[8];
    __shared__ unsigned long long sU[3];
    __shared__ int sB;
    int lane = t & 31, wid = t >> 5;
    if (t == 0) { sB = NB; sU[0] = 0ull; sU[1] = 0ull; sU[2] = 0ull; }

    // batch ALL histogram loads upfront (one round-trip)
    unsigned hf[SPAN], hn[SPAN];
    {
        const uint4* hf4 = reinterpret_cast<const uint4*>(g_hf) + t * (SPAN / 4);
        const uint4* hn4 = reinterpret_cast<const uint4*>(g_hn) + t * (SPAN / 4);
        #pragma unroll
        for (int i = 0; i < SPAN / 4; i++) {
            uint4 a = __ldcg(&hf4[i]);
            uint4 b = __ldcg(&hn4[i]);
            hf[4*i] = a.x; hf[4*i+1] = a.y; hf[4*i+2] = a.z; hf[4*i+3] = a.w;
            hn[4*i] = b.x; hn[4*i+1] = b.y; hn[4*i+2] = b.z; hn[4*i+3] = b.w;
        }
    }
    int base = t * SPAN;

    unsigned sumF = 0;
    #pragma unroll
    for (int i = 0; i < SPAN; i++) sumF += hf[i];

    // block-exclusive scan of fix counts (8 warps)
    unsigned incl = sumF;
    #pragma unroll
    for (int o = 1; o < 32; o <<= 1) {
        unsigned v = __shfl_up_sync(0xFFFFFFFFu, incl, o);
        if (lane >= o) incl += v;
    }
    if (lane == 31) swt[wid] = incl;

    // lowest fixation bin
    int mn = NB;
    #pragma unroll
    for (int i = 0; i < SPAN; i++) if (hf[i] && base + i < mn) mn = base + i;
    #pragma unroll
    for (int o = 16; o; o >>= 1) mn = min(mn, __shfl_down_sync(0xFFFFFFFFu, mn, o));
    __syncthreads();                       // swt stored + sB/sU init visible
    if (lane == 0) atomicMin(&sB, mn);
    if (t < 8) {
        unsigned w = swt[t];
        unsigned s = w;
        #pragma unroll
        for (int o = 1; o < 8; o <<= 1) {
            unsigned v = __shfl_up_sync(0xFFu, s, o);
            if (t >= o) s += v;
        }
        swt[t] = s - w;                    // exclusive warp offsets
    }
    __syncthreads();
    unsigned F = swt[wid] + (incl - sumF); // exclusive prefix of fix counts
    int bstar = sB;

    unsigned long long u1 = 0, u2 = 0, u3 = 0;
    #pragma unroll
    for (int i = 0; i < SPAN; i++) {
        u1 += (unsigned long long)hn[i] * F;       // non-fix vs fix ranked above
        u2 += (unsigned long long)hf[i] * hn[i];   // within-bin ties (expected /2)
        if (base + i > bstar) u3 += hn[i];
        F += hf[i];
    }
    #pragma unroll
    for (int o = 16; o; o >>= 1) {
        u1 += __shfl_down_sync(0xFFFFFFFFu, u1, o);
        u2 += __shfl_down_sync(0xFFFFFFFFu, u2, o);
        u3 += __shfl_down_sync(0xFFFFFFFFu, u3, o);
    }
    if (lane == 0) {
        atomicAdd(&sU[0], u1);
        atomicAdd(&sU[1], u2);
        atomicAdd(&sU[2], u3);
    }
    __syncthreads();

    // parallel FP64 per-frame epilogue on warp 0 (thread f = frame f)
    if (wid == 0) {
        double Np = (double)FRAME_ELEMS;
        double m   = __ldcg(&g_s.sum_p[lane]) / Np;
        double var = __ldcg(&g_s.sum_p2[lane]) / Np - m * m;
        double sd  = sqrt(var);
        double c   = __ldcg(&g_s.cnt_fix[lane]);
        double nssf = (__ldcg(&g_s.sum_fp[lane]) - c * m) / (sd * c);
        double simf = __ldcg(&g_s.sum_sim[lane]);
        double Nf0 = __shfl_sync(0xFFFFFFFFu, c, 0);
        #pragma unroll
        for (int o = 16; o; o >>= 1) {
            nssf += __shfl_down_sync(0xFFFFFFFFu, nssf, o);
            simf += __shfl_down_sync(0xFFFFFFFFu, simf, o);
        }
        if (lane == 0) {
            double Nf = Nf0;
            double D  = Np - Nf;
            double S  = (double)sU[0] + 0.5 * (double)sU[1];
            double b  = (double)sU[2];
            double auc = ((2.0 * Nf + 1.0) * b + 1.0 - 2.0 * S) / (2.0 * Nf * D)
                       + 1.0 - (b + 1.0) / D;
            double sim = simf / (double)FRAMES;
            double nss = nssf / (double)FRAMES;
            double loss = auc + sim + nss;
            out[0] = (float)loss;
            out[1] = (float)auc;
            out[2] = (float)sim;
            out[3] = (float)nss;
        }
    }

    // ---- self-clean device state for the next graph replay ----
    __syncthreads();   // all reads of g_hf/g_hn/g_s complete
    {
        uint4* hf4w = reinterpret_cast<uint4*>(g_hf) + t * (SPAN / 4);
        uint4* hn4w = reinterpret_cast<uint4*>(g_hn) + t * (SPAN / 4);
        uint4 z = make_uint4(0, 0, 0, 0);
        #pragma unroll
        for (int i = 0; i < SPAN / 4; i++) { hf4w[i] = z; hn4w[i] = z; }
        unsigned long long* s8 = reinterpret_cast<unsigned long long*>(&g_s);
        int n8 = (int)(sizeof(Stats) / 8);
        if (t < n8) s8[t] = 0ull;
        if (t == 0) {
            char* sc8 = reinterpret_cast<char*>(&g_s);
            for (int i = n8 * 8; i < (int)sizeof(Stats); i++) sc8[i] = 0;
            g_ticket1 = 0u;
            g_ticket2 = 0u;
        }
    }
}

extern "C" void kernel_launch(void* const* d_in, const int* in_sizes, int n_in,
                              void* d_out, int out_size) {
    const float* pred = (const float*)d_in[0];
    const float* gt   = (const float*)d_in[1];
    const int*   fix  = (const int*)d_in[2];
    float* out = (float*)d_out;

    dim3 gfull(BPF, FRAMES);
    k_main<<<gfull, TPB>>>(pred, gt, fix);
    k_sim<<<gfull, TPB>>>(pred, gt);
    k_auc<<<BPF, TPB>>>(pred, fix, out);
}